// round 7
// baseline (speedup 1.0000x reference)
#include <cuda_runtime.h>

// DistMult edge score: out[e] = sum_d node[src[e]][d] * rel[e][d] * node[dst[e]][d]
// N_NODES=100000, N_EDGES=600000, DIM=128, int32 indices.
//
// R6 finding: ptxas caps regs (~40) and serializes big register front-batches
// -> MLP through the RF is capped. Fix: stage head/tail rows through smem via
// cp.async (no register cost, no depth cap). rel rows via __ldcs LDG.128 into
// regs (keeps the evict-first hint for the 307MB stream; node table stays in L2).
//
// Block = 256 threads = 8 warps, owns 32 edges:
//   Phase 0: 64 threads stage clamped src/dst indices in smem.
//   Phase A: each thread issues 8x cp.async.cg 16B (head+tail chunks, fully
//            coalesced) + 4x LDG.128 __ldcs for its warp's rel rows.
//   Phase B: warp w reduces edges 4w..4w+3 from smem (EPW=4 butterfly).
// Per-thread MLP ~12 with ~45 regs -> smem-limited occ ~7 blocks/SM (87%).

#define DIM 128
#define EPB 32          // edges per block
#define EPW 4           // edges per warp in compute phase

__global__ __launch_bounds__(256)
void distmult_kernel(const float* __restrict__ node_emb,
                     const float* __restrict__ rel_emb,
                     const int* __restrict__ src,
                     const int* __restrict__ dst,
                     float* __restrict__ out,
                     int n_edges,
                     int n_nodes) {
    __shared__ float4 smH[EPB][32];    // head rows, 16KB
    __shared__ float4 smT[EPB][32];    // tail rows, 16KB
    __shared__ int    sIdx[2 * EPB];   // [0:32) src, [32:64) dst

    int t    = threadIdx.x;
    int warp = t >> 5;
    int lane = t & 31;
    long long eb = (long long)blockIdx.x * EPB;

    // Phase 0: stage clamped indices.
    if (t < 2 * EPB) {
        long long e = eb + (t & (EPB - 1));
        if (e >= n_edges) e = n_edges - 1;
        int v = (t < EPB) ? src[e] : dst[e];
        sIdx[t] = min(max(v, 0), n_nodes - 1);
    }
    __syncthreads();

    // Phase A1: 8 cp.async chunks per thread (2048 chunks = 32 edges x 2 rows x 32).
    // ch = i*256 + t : consecutive threads hit consecutive 16B -> coalesced.
    #pragma unroll
    for (int i = 0; i < 8; i++) {
        int ch  = i * 256 + t;
        int e   = ch >> 6;          // 64 chunks per edge (32 head + 32 tail)
        int k   = ch & 63;
        int row = k >> 5;           // 0 = head, 1 = tail
        int c   = k & 31;           // float4 column
        int idx = sIdx[row * EPB + e];
        const float4* gsrc = reinterpret_cast<const float4*>(node_emb) +
                             ((long long)idx * (DIM / 4) + c);
        float4* sdst = row ? &smT[e][c] : &smH[e][c];
        unsigned int saddr = (unsigned int)__cvta_generic_to_shared(sdst);
        asm volatile("cp.async.cg.shared.global [%0], [%1], 16;\n"
                     :: "r"(saddr), "l"(gsrc));
    }
    asm volatile("cp.async.commit_group;\n" ::: "memory");

    // Phase A2: rel rows for this warp's 4 edges (register LDG.128, streaming).
    float4 rv[EPW];
    #pragma unroll
    for (int i = 0; i < EPW; i++) {
        long long e = eb + warp * EPW + i;
        if (e >= n_edges) e = n_edges - 1;
        rv[i] = __ldcs(reinterpret_cast<const float4*>(rel_emb + e * DIM) + lane);
    }

    asm volatile("cp.async.wait_group 0;\n" ::: "memory");
    __syncthreads();

    // Phase B: compute + reduce.
    float acc[EPW];
    #pragma unroll
    for (int i = 0; i < EPW; i++) {
        int le = warp * EPW + i;
        float4 hv = smH[le][lane];
        float4 tv = smT[le][lane];
        acc[i] = hv.x * rv[i].x * tv.x
               + hv.y * rv[i].y * tv.y
               + hv.z * rv[i].z * tv.z
               + hv.w * rv[i].w * tv.w;
    }

    #pragma unroll
    for (int off = 16; off > 0; off >>= 1) {
        #pragma unroll
        for (int i = 0; i < EPW; i++)
            acc[i] += __shfl_xor_sync(0xffffffffu, acc[i], off);
    }

    if (lane < EPW) {
        long long e = eb + warp * EPW + lane;
        if (e < n_edges) {
            float v = (lane == 0) ? acc[0] : (lane == 1) ? acc[1]
                    : (lane == 2) ? acc[2] : acc[3];
            out[e] = v;
        }
    }
}

extern "C" void kernel_launch(void* const* d_in, const int* in_sizes, int n_in,
                              void* d_out, int out_size) {
    const float* node_emb = (const float*)d_in[0];
    const float* rel_emb  = (const float*)d_in[1];
    const int*   src      = (const int*)d_in[2];
    const int*   dst      = (const int*)d_in[3];
    float* out = (float*)d_out;

    int n_edges = in_sizes[1] / DIM;   // rel_emb [E,128]
    int n_nodes = in_sizes[0] / DIM;   // node_emb [N,128]

    int blocks = (n_edges + EPB - 1) / EPB;   // 18750 for E=600000
    distmult_kernel<<<blocks, 256>>>(node_emb, rel_emb, src, dst, out,
                                     n_edges, n_nodes);
}